// round 8
// baseline (speedup 1.0000x reference)
#include <cuda_runtime.h>
#include <math.h>

#define NN 100000
#define EE 1600000
#define DD 128
#define CC 47
#define P2 94   // [P|R] concat width for layer 2

// ---------------- scratch (device globals, no allocation) ----------------
__device__ int   g_deg[NN];
__device__ int   g_rowstart[NN + 1];
__device__ int   g_cursor[NN];
__device__ int   g_csrsrc[EE];
__device__ float g_agg[(size_t)NN * DD];
__device__ float g_b0[(size_t)NN * DD];
__device__ float g_b1[(size_t)NN * DD];
__device__ float g_pr[(size_t)NN * P2];
__device__ float g_stats[2 * DD];
__device__ int   g_is64;

#define SCAN_B 1024
#define SCAN_NB ((NN + SCAN_B - 1) / SCAN_B)   // 98
__device__ int g_bsum[SCAN_NB];

// ---------------- edge dtype probe ----------------
__global__ void probe_kernel(const int* __restrict__ ei32) {
    if (threadIdx.x == 0) {
        int nz = 0;
        for (int i = 0; i < 512; i++) nz += (ei32[2 * i + 1] != 0);
        g_is64 = (nz == 0) ? 1 : 0;
    }
}

__device__ __forceinline__ int edge_val(const void* ei, int is64, size_t idx) {
    if (is64) return (int)((const long long*)ei)[idx];
    return ((const int*)ei)[idx];
}

// ---------------- CSR build ----------------
__global__ void zero_deg_kernel() {
    int i = blockIdx.x * blockDim.x + threadIdx.x;
    if (i < NN) g_deg[i] = 0;
}

__global__ void deg_kernel(const void* __restrict__ ei) {
    int e = blockIdx.x * blockDim.x + threadIdx.x;
    int is64 = g_is64;
    if (e < EE) {
        int d = edge_val(ei, is64, (size_t)EE + e);
        atomicAdd(&g_deg[d], 1);
    }
}

// decoupled scan, pass 1: per-block sums
__global__ void blocksum_kernel() {
    __shared__ int ws[32];
    int i = blockIdx.x * SCAN_B + threadIdx.x;
    int v = (i < NN) ? g_deg[i] : 0;
#pragma unroll
    for (int o = 16; o; o >>= 1) v += __shfl_xor_sync(0xffffffffu, v, o);
    if ((threadIdx.x & 31) == 0) ws[threadIdx.x >> 5] = v;
    __syncthreads();
    if (threadIdx.x < 32) {
        int s = ws[threadIdx.x];
#pragma unroll
        for (int o = 16; o; o >>= 1) s += __shfl_xor_sync(0xffffffffu, s, o);
        if (threadIdx.x == 0) g_bsum[blockIdx.x] = s;
    }
}

// pass 2: exclusive scan of the 98 block sums (1 small block)
__global__ void scanbsum_kernel() {
    __shared__ int sm[128];
    int t = threadIdx.x;
    int v = (t < SCAN_NB) ? g_bsum[t] : 0;
    sm[t] = v;
    __syncthreads();
#pragma unroll
    for (int o = 1; o < 128; o <<= 1) {
        int x = (t >= o) ? sm[t - o] : 0;
        __syncthreads();
        sm[t] += x;
        __syncthreads();
    }
    if (t < SCAN_NB) g_bsum[t] = sm[t] - v;
}

// pass 3: per-block exclusive scan + block offset -> rowstart/cursor
__global__ void scanfinal_kernel() {
    __shared__ int wsum[32];
    int t = threadIdx.x;
    int lane = t & 31, wid = t >> 5;
    int i = blockIdx.x * SCAN_B + t;
    int v = (i < NN) ? g_deg[i] : 0;
    int x = v;
#pragma unroll
    for (int o = 1; o < 32; o <<= 1) {
        int u = __shfl_up_sync(0xffffffffu, x, o);
        if (lane >= o) x += u;
    }
    if (lane == 31) wsum[wid] = x;
    __syncthreads();
    if (wid == 0) {
        int s = wsum[lane];
        int y = s;
#pragma unroll
        for (int o = 1; o < 32; o <<= 1) {
            int u = __shfl_up_sync(0xffffffffu, y, o);
            if (lane >= o) y += u;
        }
        wsum[lane] = y - s;
    }
    __syncthreads();
    int excl = x - v + wsum[wid] + g_bsum[blockIdx.x];
    if (i < NN) {
        g_rowstart[i] = excl;
        g_cursor[i] = excl;
    }
    if (i == NN - 1) g_rowstart[NN] = EE;
}

__global__ void scatter_kernel(const void* __restrict__ ei) {
    int e = blockIdx.x * blockDim.x + threadIdx.x;
    int is64 = g_is64;
    if (e < EE) {
        int d = edge_val(ei, is64, (size_t)EE + e);
        int s = edge_val(ei, is64, (size_t)e);
        int p = atomicAdd(&g_cursor[d], 1);
        g_csrsrc[p] = s;
    }
}

// ---------------- mean aggregation (128-dim): warp per node ----------------
__global__ void agg_kernel(const float* __restrict__ X, float* __restrict__ AGG) {
    int warp = (blockIdx.x * blockDim.x + threadIdx.x) >> 5;
    int lane = threadIdx.x & 31;
    if (warp >= NN) return;
    int beg = g_rowstart[warp];
    int end = g_rowstart[warp + 1];
    float4 acc = make_float4(0.f, 0.f, 0.f, 0.f);
    for (int e = beg; e < end; e++) {
        int s = g_csrsrc[e];
        float4 v = *reinterpret_cast<const float4*>(X + (size_t)s * DD + lane * 4);
        acc.x += v.x; acc.y += v.y; acc.z += v.z; acc.w += v.w;
    }
    int cnt = end - beg;
    float inv = 1.0f / (float)(cnt > 0 ? cnt : 1);
    acc.x *= inv; acc.y *= inv; acc.z *= inv; acc.w *= inv;
    *reinterpret_cast<float4*>(AGG + (size_t)warp * DD + lane * 4) = acc;
}

// ---------------- fused GEMM (layers 0/1): Y = AGG@Wl + X@Wr + bias ----------------
// 128x128 tile, BK=16 over K=256 logical, 256 threads, 8x8 per thread.
__global__ void __launch_bounds__(256, 2)
gemm128_kernel(const float* __restrict__ A, const float* __restrict__ X,
               const float* __restrict__ Wl, const float* __restrict__ Wr,
               const float* __restrict__ bias, float* __restrict__ Y) {
    __shared__ float As[16][128];
    __shared__ float Bs[16][128];
    const int tid = threadIdx.x;
    const int tx = tid & 15, ty = tid >> 4;
    const int nbase = blockIdx.x * 128;

    const int lr = tid >> 2;          // 0..63
    const int lk = (tid & 3) * 4;     // 0,4,8,12
    const int bk = tid >> 5;          // 0..7
    const int bc = (tid & 31) * 4;    // 0..124

    float acc[8][8];
#pragma unroll
    for (int i = 0; i < 8; i++)
#pragma unroll
        for (int j = 0; j < 8; j++) acc[i][j] = 0.f;

#pragma unroll 1
    for (int kt = 0; kt < 16; kt++) {
        const float* Asrc = (kt < 8) ? A : X;
        const float* W    = (kt < 8) ? Wl : Wr;
        const int kofs = (kt & 7) * 16;

#pragma unroll
        for (int h = 0; h < 2; h++) {
            int r = lr + h * 64;
            int n = nbase + r;
            if (n >= NN) n = NN - 1;   // clamp; rows guarded at store
            float4 v = *reinterpret_cast<const float4*>(Asrc + (size_t)n * DD + kofs + lk);
            As[lk + 0][r] = v.x;
            As[lk + 1][r] = v.y;
            As[lk + 2][r] = v.z;
            As[lk + 3][r] = v.w;
        }
#pragma unroll
        for (int h = 0; h < 2; h++) {
            int k = bk + h * 8;
            float4 w = *reinterpret_cast<const float4*>(W + (size_t)(kofs + k) * DD + bc);
            *reinterpret_cast<float4*>(&Bs[k][bc]) = w;
        }
        __syncthreads();

#pragma unroll
        for (int k = 0; k < 16; k++) {
            float a[8], b[8];
            *reinterpret_cast<float4*>(a)     = *reinterpret_cast<float4*>(&As[k][ty * 8]);
            *reinterpret_cast<float4*>(a + 4) = *reinterpret_cast<float4*>(&As[k][ty * 8 + 4]);
            *reinterpret_cast<float4*>(b)     = *reinterpret_cast<float4*>(&Bs[k][tx * 8]);
            *reinterpret_cast<float4*>(b + 4) = *reinterpret_cast<float4*>(&Bs[k][tx * 8 + 4]);
#pragma unroll
            for (int i = 0; i < 8; i++)
#pragma unroll
                for (int j = 0; j < 8; j++) acc[i][j] += a[i] * b[j];
        }
        __syncthreads();
    }

    float bs[8];
#pragma unroll
    for (int j = 0; j < 8; j++) bs[j] = bias[tx * 8 + j];
#pragma unroll
    for (int i = 0; i < 8; i++) {
        int n = nbase + ty * 8 + i;
        if (n >= NN) continue;
        float4 o0, o1;
        o0.x = acc[i][0] + bs[0]; o0.y = acc[i][1] + bs[1];
        o0.z = acc[i][2] + bs[2]; o0.w = acc[i][3] + bs[3];
        o1.x = acc[i][4] + bs[4]; o1.y = acc[i][5] + bs[5];
        o1.z = acc[i][6] + bs[6]; o1.w = acc[i][7] + bs[7];
        float4* yp = reinterpret_cast<float4*>(Y + (size_t)n * DD + tx * 8);
        yp[0] = o0;
        yp[1] = o1;
    }
}

// ---------------- layer-2 GEMM: [P|R] = h1 @ [Wl2|Wr2]  (K=128, NOUT=94) ----------------
__global__ void __launch_bounds__(256, 2)
gemm2_kernel(const float* __restrict__ H, const float* __restrict__ Wl,
             const float* __restrict__ Wr, float* __restrict__ PR) {
    __shared__ float As[16][128];
    __shared__ float Bs[16][128];
    const int tid = threadIdx.x;
    const int tx = tid & 15, ty = tid >> 4;
    const int nbase = blockIdx.x * 128;

    const int lr = tid >> 2;
    const int lk = (tid & 3) * 4;
    const int wk = tid >> 4;          // 0..15
    const int wc0 = (tid & 15) * 8;   // 0..120

    float acc[8][8];
#pragma unroll
    for (int i = 0; i < 8; i++)
#pragma unroll
        for (int j = 0; j < 8; j++) acc[i][j] = 0.f;

#pragma unroll 1
    for (int kt = 0; kt < 8; kt++) {
        const int kofs = kt * 16;
#pragma unroll
        for (int h = 0; h < 2; h++) {
            int r = lr + h * 64;
            int n = nbase + r;
            if (n >= NN) n = NN - 1;
            float4 v = *reinterpret_cast<const float4*>(H + (size_t)n * DD + kofs + lk);
            As[lk + 0][r] = v.x;
            As[lk + 1][r] = v.y;
            As[lk + 2][r] = v.z;
            As[lk + 3][r] = v.w;
        }
        {
            int krow = kofs + wk;
#pragma unroll
            for (int j = 0; j < 8; j++) {
                int c = wc0 + j;
                float w = 0.f;
                if (c < CC) w = Wl[krow * CC + c];
                else if (c < P2) w = Wr[krow * CC + (c - CC)];
                Bs[wk][c] = w;
            }
        }
        __syncthreads();

#pragma unroll
        for (int k = 0; k < 16; k++) {
            float a[8], b[8];
            *reinterpret_cast<float4*>(a)     = *reinterpret_cast<float4*>(&As[k][ty * 8]);
            *reinterpret_cast<float4*>(a + 4) = *reinterpret_cast<float4*>(&As[k][ty * 8 + 4]);
            *reinterpret_cast<float4*>(b)     = *reinterpret_cast<float4*>(&Bs[k][tx * 8]);
            *reinterpret_cast<float4*>(b + 4) = *reinterpret_cast<float4*>(&Bs[k][tx * 8 + 4]);
#pragma unroll
            for (int i = 0; i < 8; i++)
#pragma unroll
                for (int j = 0; j < 8; j++) acc[i][j] += a[i] * b[j];
        }
        __syncthreads();
    }

#pragma unroll
    for (int i = 0; i < 8; i++) {
        int n = nbase + ty * 8 + i;
        if (n >= NN) continue;
#pragma unroll
        for (int j = 0; j < 8; j++) {
            int c = tx * 8 + j;
            if (c < P2) PR[(size_t)n * P2 + c] = acc[i][j];
        }
    }
}

// ---------------- batchnorm stats / apply ----------------
__global__ void zero_stats_kernel() {
    int i = threadIdx.x;
    if (i < 2 * DD) g_stats[i] = 0.f;
}

__global__ void stats_kernel(const float* __restrict__ Y) {
    int col = threadIdx.x;
    int r0 = blockIdx.x * 256;
    float s = 0.f, sq = 0.f;
    int rend = r0 + 256;
    if (rend > NN) rend = NN;
    for (int r = r0; r < rend; r++) {
        float v = Y[(size_t)r * DD + col];
        s += v;
        sq += v * v;
    }
    atomicAdd(&g_stats[col], s);
    atomicAdd(&g_stats[DD + col], sq);
}

__global__ void apply_kernel(float* __restrict__ Y, const float* __restrict__ g,
                             const float* __restrict__ b) {
    int idx = blockIdx.x * blockDim.x + threadIdx.x;
    const int total4 = NN * DD / 4;
    if (idx >= total4) return;
    int col4 = (idx & (DD / 4 - 1)) * 4;
    float4 v = reinterpret_cast<float4*>(Y)[idx];
    float o[4] = {v.x, v.y, v.z, v.w};
#pragma unroll
    for (int q = 0; q < 4; q++) {
        int c = col4 + q;
        float mu = g_stats[c] * (1.0f / NN);
        float var = g_stats[DD + c] * (1.0f / NN) - mu * mu;
        float scale = rsqrtf(var + 1e-5f) * g[c];
        float shift = b[c] - mu * scale;
        o[q] = fmaxf(o[q] * scale + shift, 0.f);
    }
    v.x = o[0]; v.y = o[1]; v.z = o[2]; v.w = o[3];
    reinterpret_cast<float4*>(Y)[idx] = v;
}

// ---------------- fused layer-2 tail: mean-agg(P) + R + bias, then log_softmax ----------------
__global__ void agg_lsm_kernel(const float* __restrict__ PR, const float* __restrict__ bl2,
                               float* __restrict__ out) {
    int row = blockIdx.x * 8 + (threadIdx.x >> 5);
    int lane = threadIdx.x & 31;
    if (row >= NN) return;
    int beg = g_rowstart[row];
    int end = g_rowstart[row + 1];
    float s0 = 0.f, s1 = 0.f;
    for (int e = beg; e < end; e++) {
        int src = g_csrsrc[e];
        const float* pr = PR + (size_t)src * P2;
        if (lane < CC) s0 += pr[lane];
        if (lane + 32 < CC) s1 += pr[lane + 32];
    }
    int cnt = end - beg;
    float inv = 1.0f / (float)(cnt > 0 ? cnt : 1);
    const float* prn = PR + (size_t)row * P2;
    float v0 = (lane < CC) ? s0 * inv + prn[CC + lane] + bl2[lane] : -INFINITY;
    float v1 = (lane + 32 < CC) ? s1 * inv + prn[CC + lane + 32] + bl2[lane + 32] : -INFINITY;

    float m = fmaxf(v0, v1);
#pragma unroll
    for (int o = 16; o > 0; o >>= 1) m = fmaxf(m, __shfl_xor_sync(0xffffffffu, m, o));
    float s = ((lane < CC) ? expf(v0 - m) : 0.f) + ((lane + 32 < CC) ? expf(v1 - m) : 0.f);
#pragma unroll
    for (int o = 16; o > 0; o >>= 1) s += __shfl_xor_sync(0xffffffffu, s, o);
    float l = m + logf(s);
    float* p = out + (size_t)row * CC;
    if (lane < CC) p[lane] = v0 - l;
    if (lane + 32 < CC) p[lane + 32] = v1 - l;
}

// ---------------- launch ----------------
extern "C" void kernel_launch(void* const* d_in, const int* in_sizes, int n_in,
                              void* d_out, int out_size) {
    const float* x   = (const float*)d_in[0];
    const void*  ei  = d_in[1];
    const float* Wl0 = (const float*)d_in[2];
    const float* bl0 = (const float*)d_in[3];
    const float* Wr0 = (const float*)d_in[4];
    const float* g0  = (const float*)d_in[5];
    const float* be0 = (const float*)d_in[6];
    const float* Wl1 = (const float*)d_in[7];
    const float* bl1 = (const float*)d_in[8];
    const float* Wr1 = (const float*)d_in[9];
    const float* g1  = (const float*)d_in[10];
    const float* be1 = (const float*)d_in[11];
    const float* Wl2 = (const float*)d_in[12];
    const float* bl2 = (const float*)d_in[13];
    const float* Wr2 = (const float*)d_in[14];
    float* out = (float*)d_out;

    void* p;
    cudaGetSymbolAddress(&p, g_agg); float* aggp = (float*)p;
    cudaGetSymbolAddress(&p, g_b0);  float* b0p  = (float*)p;
    cudaGetSymbolAddress(&p, g_b1);  float* b1p  = (float*)p;
    cudaGetSymbolAddress(&p, g_pr);  float* prp  = (float*)p;

    // edge dtype probe + CSR build (decoupled scan)
    probe_kernel<<<1, 32>>>((const int*)ei);
    zero_deg_kernel<<<(NN + 255) / 256, 256>>>();
    deg_kernel<<<(EE + 255) / 256, 256>>>(ei);
    blocksum_kernel<<<SCAN_NB, SCAN_B>>>();
    scanbsum_kernel<<<1, 128>>>();
    scanfinal_kernel<<<SCAN_NB, SCAN_B>>>();
    scatter_kernel<<<(EE + 255) / 256, 256>>>(ei);

    const int gemm_blocks = (NN + 127) / 128;
    const int agg_blocks = (NN * 32 + 255) / 256;
    const int apply_blocks = (NN * DD / 4 + 255) / 256;
    const int stats_blocks = (NN + 255) / 256;

    // layer 0
    agg_kernel<<<agg_blocks, 256>>>(x, aggp);
    gemm128_kernel<<<gemm_blocks, 256>>>(aggp, x, Wl0, Wr0, bl0, b0p);
    zero_stats_kernel<<<1, 256>>>();
    stats_kernel<<<stats_blocks, 128>>>(b0p);
    apply_kernel<<<apply_blocks, 256>>>(b0p, g0, be0);

    // layer 1
    agg_kernel<<<agg_blocks, 256>>>(b0p, aggp);
    gemm128_kernel<<<gemm_blocks, 256>>>(aggp, b0p, Wl1, Wr1, bl1, b1p);
    zero_stats_kernel<<<1, 256>>>();
    stats_kernel<<<stats_blocks, 128>>>(b1p);
    apply_kernel<<<apply_blocks, 256>>>(b1p, g1, be1);

    // layer 2: [P|R] = h1 @ [Wl2|Wr2]; then fused agg(P)+R+bias+log_softmax
    gemm2_kernel<<<gemm_blocks, 256>>>(b1p, Wl2, Wr2, prp);
    agg_lsm_kernel<<<(NN + 7) / 8, 256>>>(prp, bl2, out);
}

// round 10
// speedup vs baseline: 2.1141x; 2.1141x over previous
#include <cuda_runtime.h>
#include <cuda_bf16.h>
#include <math.h>
#include <stdint.h>

#define NN 100000
#define EE 1600000
#define DD 128
#define CC 47
#define PRW 96   // [P(47) | R(47) | pad(2)] width for layer 2

// ==================== scratch (device globals, no allocation) ====================
__device__ int   g_deg[NN];
__device__ int   g_rowstart[NN + 1];
__device__ int   g_cursor[NN];
__device__ int   g_csrsrc[EE];
__device__ float g_agg[(size_t)NN * DD];
__device__ float g_b0[(size_t)NN * DD];
__device__ float g_b1[(size_t)NN * DD];
__device__ float g_pr[(size_t)NN * PRW];
__device__ float g_stats[2 * DD];
__device__ int   g_is64;
// W^T images, bf16 hi/lo: layers 0/1: [128 n][256 k]; layer 2: [96 n][128 k]
__device__ __nv_bfloat16 g_w01hi[2][128 * 256];
__device__ __nv_bfloat16 g_w01lo[2][128 * 256];
__device__ __nv_bfloat16 g_w2hi[PRW * 128];
__device__ __nv_bfloat16 g_w2lo[PRW * 128];

#define SCAN_B 1024
#define SCAN_NB ((NN + SCAN_B - 1) / SCAN_B)
__device__ int g_bsum[SCAN_NB];

// ==================== PTX helpers (baseline ISA, no 'a' features) ====================
static __device__ __forceinline__ uint32_t smem_u32(const void* p) {
    uint32_t a;
    asm("{ .reg .u64 t; cvta.to.shared.u64 t, %1; cvt.u32.u64 %0, t; }" : "=r"(a) : "l"(p));
    return a;
}
#define LDSM4(r, a) \
    asm volatile("ldmatrix.sync.aligned.m8n8.x4.shared.b16 {%0,%1,%2,%3}, [%4];" \
                 : "=r"((r)[0]), "=r"((r)[1]), "=r"((r)[2]), "=r"((r)[3]) : "r"(a))
#define MMA16816(d, a, b0, b1) \
    asm volatile("mma.sync.aligned.m16n8k16.row.col.f32.bf16.bf16.f32 " \
                 "{%0,%1,%2,%3}, {%4,%5,%6,%7}, {%8,%9}, {%0,%1,%2,%3};" \
                 : "+f"((d)[0]), "+f"((d)[1]), "+f"((d)[2]), "+f"((d)[3]) \
                 : "r"((a)[0]), "r"((a)[1]), "r"((a)[2]), "r"((a)[3]), "r"(b0), "r"(b1))

// ==================== edge dtype probe ====================
__global__ void probe_kernel(const int* __restrict__ ei32) {
    if (threadIdx.x == 0) {
        int nz = 0;
        for (int i = 0; i < 512; i++) nz += (ei32[2 * i + 1] != 0);
        g_is64 = (nz == 0) ? 1 : 0;
    }
}
__device__ __forceinline__ int edge_val(const void* ei, int is64, size_t idx) {
    if (is64) return (int)((const long long*)ei)[idx];
    return ((const int*)ei)[idx];
}

// ==================== CSR build ====================
__global__ void zero_deg_kernel() {
    int i = blockIdx.x * blockDim.x + threadIdx.x;
    if (i < NN) g_deg[i] = 0;
}
__global__ void deg_kernel(const void* __restrict__ ei) {
    int e = blockIdx.x * blockDim.x + threadIdx.x;
    int is64 = g_is64;
    if (e < EE) atomicAdd(&g_deg[edge_val(ei, is64, (size_t)EE + e)], 1);
}
__global__ void blocksum_kernel() {
    __shared__ int ws[32];
    int i = blockIdx.x * SCAN_B + threadIdx.x;
    int v = (i < NN) ? g_deg[i] : 0;
#pragma unroll
    for (int o = 16; o; o >>= 1) v += __shfl_xor_sync(0xffffffffu, v, o);
    if ((threadIdx.x & 31) == 0) ws[threadIdx.x >> 5] = v;
    __syncthreads();
    if (threadIdx.x < 32) {
        int s = ws[threadIdx.x];
#pragma unroll
        for (int o = 16; o; o >>= 1) s += __shfl_xor_sync(0xffffffffu, s, o);
        if (threadIdx.x == 0) g_bsum[blockIdx.x] = s;
    }
}
__global__ void scanbsum_kernel() {
    __shared__ int sm[128];
    int t = threadIdx.x;
    int v = (t < SCAN_NB) ? g_bsum[t] : 0;
    sm[t] = v;
    __syncthreads();
#pragma unroll
    for (int o = 1; o < 128; o <<= 1) {
        int x = (t >= o) ? sm[t - o] : 0;
        __syncthreads();
        sm[t] += x;
        __syncthreads();
    }
    if (t < SCAN_NB) g_bsum[t] = sm[t] - v;
}
__global__ void scanfinal_kernel() {
    __shared__ int wsum[32];
    int t = threadIdx.x;
    int lane = t & 31, wid = t >> 5;
    int i = blockIdx.x * SCAN_B + t;
    int v = (i < NN) ? g_deg[i] : 0;
    int x = v;
#pragma unroll
    for (int o = 1; o < 32; o <<= 1) {
        int u = __shfl_up_sync(0xffffffffu, x, o);
        if (lane >= o) x += u;
    }
    if (lane == 31) wsum[wid] = x;
    __syncthreads();
    if (wid == 0) {
        int s = wsum[lane];
        int y = s;
#pragma unroll
        for (int o = 1; o < 32; o <<= 1) {
            int u = __shfl_up_sync(0xffffffffu, y, o);
            if (lane >= o) y += u;
        }
        wsum[lane] = y - s;
    }
    __syncthreads();
    int excl = x - v + wsum[wid] + g_bsum[blockIdx.x];
    if (i < NN) {
        g_rowstart[i] = excl;
        g_cursor[i] = excl;
    }
    if (i == NN - 1) g_rowstart[NN] = EE;
}
__global__ void scatter_kernel(const void* __restrict__ ei) {
    int e = blockIdx.x * blockDim.x + threadIdx.x;
    int is64 = g_is64;
    if (e < EE) {
        int d = edge_val(ei, is64, (size_t)EE + e);
        int s = edge_val(ei, is64, (size_t)e);
        int p = atomicAdd(&g_cursor[d], 1);
        g_csrsrc[p] = s;
    }
}

// ==================== weight conversion: fp32 -> W^T bf16 hi/lo ====================
__global__ void conv_w01_kernel(const float* __restrict__ Wl0, const float* __restrict__ Wr0,
                                const float* __restrict__ Wl1, const float* __restrict__ Wr1) {
    int idx = blockIdx.x * blockDim.x + threadIdx.x;
    if (idx >= 2 * 128 * 256) return;
    int layer = idx >> 15;
    int r = idx & 32767;
    int n = r >> 8;          // output col 0..127
    int k = r & 255;         // logical K 0..255
    const float* Wl = layer ? Wl1 : Wl0;
    const float* Wr = layer ? Wr1 : Wr0;
    float v = (k < 128) ? Wl[k * 128 + n] : Wr[(k - 128) * 128 + n];
    __nv_bfloat16 hi = __float2bfloat16_rn(v);
    __nv_bfloat16 lo = __float2bfloat16_rn(v - __bfloat162float(hi));
    g_w01hi[layer][n * 256 + k] = hi;
    g_w01lo[layer][n * 256 + k] = lo;
}
__global__ void conv_w2_kernel(const float* __restrict__ Wl2, const float* __restrict__ Wr2) {
    int idx = blockIdx.x * blockDim.x + threadIdx.x;
    if (idx >= PRW * 128) return;
    int n = idx >> 7;   // 0..95
    int k = idx & 127;
    float v = 0.f;
    if (n < CC) v = Wl2[k * CC + n];
    else if (n < 2 * CC) v = Wr2[k * CC + (n - CC)];
    __nv_bfloat16 hi = __float2bfloat16_rn(v);
    __nv_bfloat16 lo = __float2bfloat16_rn(v - __bfloat162float(hi));
    g_w2hi[n * 128 + k] = hi;
    g_w2lo[n * 128 + k] = lo;
}

// ==================== mean aggregation (fp32, warp per node) ====================
__global__ void agg_kernel(const float* __restrict__ X, float* __restrict__ AGG) {
    int warp = (blockIdx.x * blockDim.x + threadIdx.x) >> 5;
    int lane = threadIdx.x & 31;
    if (warp >= NN) return;
    int beg = g_rowstart[warp];
    int end = g_rowstart[warp + 1];
    float4 acc = make_float4(0.f, 0.f, 0.f, 0.f);
    for (int e = beg; e < end; e++) {
        int s = g_csrsrc[e];
        float4 v = *reinterpret_cast<const float4*>(X + (size_t)s * DD + lane * 4);
        acc.x += v.x; acc.y += v.y; acc.z += v.z; acc.w += v.w;
    }
    int cnt = end - beg;
    float inv = 1.0f / (float)(cnt > 0 ? cnt : 1);
    acc.x *= inv; acc.y *= inv; acc.z *= inv; acc.w *= inv;
    *reinterpret_cast<float4*>(AGG + (size_t)warp * DD + lane * 4) = acc;
}

// ==================== HMMA split-bf16 GEMM ====================
// Y[M,NT] = A(K=NCHUNK*128 logical)@W + bias.  3-term split: Ahi*Whi + Ahi*Wlo + Alo*Whi.
// CTA: 128 rows x NT cols. 8 warps: 4 in m (32 rows) x 2 in n (NT/2 cols).
// smem: padded row stride 272B (128 bf16 + 8 pad) — ldmatrix/STS conflict-free.
#define STRIDE_B 272
template <int NT, int NCHUNK>
__global__ void __launch_bounds__(256, 1)
gemm_mma(const float* __restrict__ A0, const float* __restrict__ A1,
         const __nv_bfloat16* __restrict__ Whi, const __nv_bfloat16* __restrict__ Wlo,
         const float* __restrict__ bias, float* __restrict__ Y, int ldY) {
    extern __shared__ char smem[];
    constexpr int AHI = 0;
    constexpr int ALO = 128 * STRIDE_B;
    constexpr int WHI = 2 * 128 * STRIDE_B;
    constexpr int WLO = WHI + NT * STRIDE_B;
    constexpr int NB4 = NT / 32;       // x4 B-loads per warp per kstep (cover 16 n each)
    constexpr int NTJ = NT / 16;       // n8 tiles per warp

    const uint32_t sb = smem_u32(smem);
    const int tid = threadIdx.x;
    const int wid = tid >> 5, lane = tid & 31;
    const int warp_m = wid & 3, warp_n = wid >> 2;
    const int nbase = blockIdx.x * 128;

    float acc[2][NTJ][4];
#pragma unroll
    for (int i = 0; i < 2; i++)
#pragma unroll
        for (int j = 0; j < NTJ; j++)
#pragma unroll
            for (int q = 0; q < 4; q++) acc[i][j][q] = 0.f;

    // ldmatrix per-lane address components
    const int lt = lane >> 3, lrow = lane & 7;
    const int a_m = warp_m * 32 + lrow + ((lt & 1) << 3);
    const int a_k = (lt >> 1) << 3;
    const int b_n = warp_n * (NT / 2) + lrow + ((lt >> 1) << 3);
    const int b_k = (lt & 1) << 3;

#pragma unroll 1
    for (int c = 0; c < NCHUNK; c++) {
        const float* Asrc = (NCHUNK == 2 && c == 1) ? A1 : A0;
        // ---- A chunk: 128 rows x 128 fp32 -> bf16 hi/lo ----
        for (int i = tid; i < 4096; i += 256) {
            int r = i >> 5, q = i & 31;
            int n = nbase + r;
            if (n >= NN) n = NN - 1;
            float4 v = __ldg(reinterpret_cast<const float4*>(Asrc + (size_t)n * DD) + q);
            __nv_bfloat16 hx = __float2bfloat16_rn(v.x);
            __nv_bfloat16 hy = __float2bfloat16_rn(v.y);
            __nv_bfloat16 hz = __float2bfloat16_rn(v.z);
            __nv_bfloat16 hw = __float2bfloat16_rn(v.w);
            __nv_bfloat16 lx = __float2bfloat16_rn(v.x - __bfloat162float(hx));
            __nv_bfloat16 ly = __float2bfloat16_rn(v.y - __bfloat162float(hy));
            __nv_bfloat16 lz = __float2bfloat16_rn(v.z - __bfloat162float(hz));
            __nv_bfloat16 lw = __float2bfloat16_rn(v.w - __bfloat162float(hw));
            uint2 hp, lp;
            hp.x = (uint32_t)__bfloat16_as_ushort(hx) | ((uint32_t)__bfloat16_as_ushort(hy) << 16);
            hp.y = (uint32_t)__bfloat16_as_ushort(hz) | ((uint32_t)__bfloat16_as_ushort(hw) << 16);
            lp.x = (uint32_t)__bfloat16_as_ushort(lx) | ((uint32_t)__bfloat16_as_ushort(ly) << 16);
            lp.y = (uint32_t)__bfloat16_as_ushort(lz) | ((uint32_t)__bfloat16_as_ushort(lw) << 16);
            int off = r * STRIDE_B + q * 8;
            *reinterpret_cast<uint2*>(smem + AHI + off) = hp;
            *reinterpret_cast<uint2*>(smem + ALO + off) = lp;
        }
        // ---- W chunk: NT rows x 128 bf16 hi/lo (row-major W^T, row stride NCHUNK*128) ----
        for (int i = tid; i < NT * 16; i += 256) {
            int n = i >> 4, u4 = i & 15;
            size_t gofs = (size_t)n * (NCHUNK * 128) + c * 128 + u4 * 8;
            int off = n * STRIDE_B + u4 * 16;
            *reinterpret_cast<uint4*>(smem + WHI + off) =
                *reinterpret_cast<const uint4*>(Whi + gofs);
            *reinterpret_cast<uint4*>(smem + WLO + off) =
                *reinterpret_cast<const uint4*>(Wlo + gofs);
        }
        __syncthreads();

        // ---- mainloop: 8 k16-steps per chunk ----
#pragma unroll
        for (int ks = 0; ks < 8; ks++) {
            const int kb = ks * 16;
            uint32_t ahi[2][4], alo[2][4], bhi[NB4][4], blo[NB4][4];
#pragma unroll
            for (int mi = 0; mi < 2; mi++) {
                uint32_t ad = sb + AHI + (a_m + mi * 16) * STRIDE_B + (kb + a_k) * 2;
                LDSM4(ahi[mi], ad);
                LDSM4(alo[mi], ad + (ALO - AHI));
            }
#pragma unroll
            for (int g = 0; g < NB4; g++) {
                uint32_t bd = sb + WHI + (b_n + g * 16) * STRIDE_B + (kb + b_k) * 2;
                LDSM4(bhi[g], bd);
                LDSM4(blo[g], bd + (WLO - WHI));
            }
#pragma unroll
            for (int mi = 0; mi < 2; mi++)
#pragma unroll
                for (int g = 0; g < NB4; g++)
#pragma unroll
                    for (int h = 0; h < 2; h++) {
                        int j = g * 2 + h;
                        MMA16816(acc[mi][j], ahi[mi], bhi[g][h * 2], bhi[g][h * 2 + 1]);
                        MMA16816(acc[mi][j], ahi[mi], blo[g][h * 2], blo[g][h * 2 + 1]);
                        MMA16816(acc[mi][j], alo[mi], bhi[g][h * 2], bhi[g][h * 2 + 1]);
                    }
        }
        __syncthreads();
    }

    // ---- epilogue ----
    const int mrow = nbase + warp_m * 32 + (lane >> 2);
#pragma unroll
    for (int j = 0; j < NTJ; j++) {
        int col = warp_n * (NT / 2) + j * 8 + (lane & 3) * 2;
        float bx = bias ? bias[col] : 0.f;
        float by = bias ? bias[col + 1] : 0.f;
#pragma unroll
        for (int mi = 0; mi < 2; mi++) {
            int m0 = mrow + mi * 16;
            if (m0 < NN) {
                float2 o = make_float2(acc[mi][j][0] + bx, acc[mi][j][1] + by);
                *reinterpret_cast<float2*>(Y + (size_t)m0 * ldY + col) = o;
            }
            int m1 = m0 + 8;
            if (m1 < NN) {
                float2 o = make_float2(acc[mi][j][2] + bx, acc[mi][j][3] + by);
                *reinterpret_cast<float2*>(Y + (size_t)m1 * ldY + col) = o;
            }
        }
    }
}

// ==================== batchnorm stats / apply ====================
__global__ void zero_stats_kernel() {
    int i = threadIdx.x;
    if (i < 2 * DD) g_stats[i] = 0.f;
}
__global__ void stats_kernel(const float* __restrict__ Y) {
    int col = threadIdx.x;
    int r0 = blockIdx.x * 256;
    float s = 0.f, sq = 0.f;
    int rend = r0 + 256;
    if (rend > NN) rend = NN;
    for (int r = r0; r < rend; r++) {
        float v = Y[(size_t)r * DD + col];
        s += v;
        sq += v * v;
    }
    atomicAdd(&g_stats[col], s);
    atomicAdd(&g_stats[DD + col], sq);
}
__global__ void apply_kernel(float* __restrict__ Y, const float* __restrict__ g,
                             const float* __restrict__ b) {
    int idx = blockIdx.x * blockDim.x + threadIdx.x;
    const int total4 = NN * DD / 4;
    if (idx >= total4) return;
    int col4 = (idx & (DD / 4 - 1)) * 4;
    float4 v = reinterpret_cast<float4*>(Y)[idx];
    float o[4] = {v.x, v.y, v.z, v.w};
#pragma unroll
    for (int q = 0; q < 4; q++) {
        int c = col4 + q;
        float mu = g_stats[c] * (1.0f / NN);
        float var = g_stats[DD + c] * (1.0f / NN) - mu * mu;
        float scale = rsqrtf(var + 1e-5f) * g[c];
        float shift = b[c] - mu * scale;
        o[q] = fmaxf(o[q] * scale + shift, 0.f);
    }
    v.x = o[0]; v.y = o[1]; v.z = o[2]; v.w = o[3];
    reinterpret_cast<float4*>(Y)[idx] = v;
}

// ==================== fused layer-2 tail: mean-agg(P) + R + bias -> log_softmax ====================
__global__ void agg_lsm_kernel(const float* __restrict__ PR, const float* __restrict__ bl2,
                               float* __restrict__ out) {
    int row = blockIdx.x * 8 + (threadIdx.x >> 5);
    int lane = threadIdx.x & 31;
    if (row >= NN) return;
    int beg = g_rowstart[row];
    int end = g_rowstart[row + 1];
    float s0 = 0.f, s1 = 0.f;
    for (int e = beg; e < end; e++) {
        int src = g_csrsrc[e];
        const float* pr = PR + (size_t)src * PRW;
        if (lane < CC) s0 += pr[lane];
        if (lane + 32 < CC) s1 += pr[lane + 32];
    }
    int cnt = end - beg;
    float inv = 1.0f / (float)(cnt > 0 ? cnt : 1);
    const float* prn = PR + (size_t)row * PRW;
    float v0 = (lane < CC) ? s0 * inv + prn[CC + lane] + bl2[lane] : -INFINITY;
    float v1 = (lane + 32 < CC) ? s1 * inv + prn[CC + lane + 32] + bl2[lane + 32] : -INFINITY;

    float m = fmaxf(v0, v1);
#pragma unroll
    for (int o = 16; o > 0; o >>= 1) m = fmaxf(m, __shfl_xor_sync(0xffffffffu, m, o));
    float s = ((lane < CC) ? expf(v0 - m) : 0.f) + ((lane + 32 < CC) ? expf(v1 - m) : 0.f);
#pragma unroll
    for (int o = 16; o > 0; o >>= 1) s += __shfl_xor_sync(0xffffffffu, s, o);
    float l = m + logf(s);
    float* p = out + (size_t)row * CC;
    if (lane < CC) p[lane] = v0 - l;
    if (lane + 32 < CC) p[lane + 32] = v1 - l;
}

// ==================== launch ====================
extern "C" void kernel_launch(void* const* d_in, const int* in_sizes, int n_in,
                              void* d_out, int out_size) {
    const float* x   = (const float*)d_in[0];
    const void*  ei  = d_in[1];
    const float* Wl0 = (const float*)d_in[2];
    const float* bl0 = (const float*)d_in[3];
    const float* Wr0 = (const float*)d_in[4];
    const float* g0  = (const float*)d_in[5];
    const float* be0 = (const float*)d_in[6];
    const float* Wl1 = (const float*)d_in[7];
    const float* bl1 = (const float*)d_in[8];
    const float* Wr1 = (const float*)d_in[9];
    const float* g1  = (const float*)d_in[10];
    const float* be1 = (const float*)d_in[11];
    const float* Wl2 = (const float*)d_in[12];
    const float* bl2 = (const float*)d_in[13];
    const float* Wr2 = (const float*)d_in[14];
    float* out = (float*)d_out;

    void* p;
    cudaGetSymbolAddress(&p, g_agg);   float* aggp = (float*)p;
    cudaGetSymbolAddress(&p, g_b0);    float* b0p  = (float*)p;
    cudaGetSymbolAddress(&p, g_b1);    float* b1p  = (float*)p;
    cudaGetSymbolAddress(&p, g_pr);    float* prp  = (float*)p;
    cudaGetSymbolAddress(&p, g_w01hi); __nv_bfloat16* w01hi = (__nv_bfloat16*)p;
    cudaGetSymbolAddress(&p, g_w01lo); __nv_bfloat16* w01lo = (__nv_bfloat16*)p;
    cudaGetSymbolAddress(&p, g_w2hi);  __nv_bfloat16* w2hi  = (__nv_bfloat16*)p;
    cudaGetSymbolAddress(&p, g_w2lo);  __nv_bfloat16* w2lo  = (__nv_bfloat16*)p;

    const int SMEM01 = 2 * 128 * STRIDE_B + 2 * 128 * STRIDE_B;  // 139264
    const int SMEM2  = 2 * 128 * STRIDE_B + 2 * PRW * STRIDE_B;  // 121856
    cudaFuncSetAttribute((const void*)gemm_mma<128, 2>,
                         cudaFuncAttributeMaxDynamicSharedMemorySize, SMEM01);
    cudaFuncSetAttribute((const void*)gemm_mma<PRW, 1>,
                         cudaFuncAttributeMaxDynamicSharedMemorySize, SMEM2);

    // edge dtype probe + CSR build
    probe_kernel<<<1, 32>>>((const int*)ei);
    zero_deg_kernel<<<(NN + 255) / 256, 256>>>();
    deg_kernel<<<(EE + 255) / 256, 256>>>(ei);
    blocksum_kernel<<<SCAN_NB, SCAN_B>>>();
    scanbsum_kernel<<<1, 128>>>();
    scanfinal_kernel<<<SCAN_NB, SCAN_B>>>();
    scatter_kernel<<<(EE + 255) / 256, 256>>>(ei);

    // weight conversion to W^T bf16 hi/lo
    conv_w01_kernel<<<(2 * 128 * 256 + 255) / 256, 256>>>(Wl0, Wr0, Wl1, Wr1);
    conv_w2_kernel<<<(PRW * 128 + 255) / 256, 256>>>(Wl2, Wr2);

    const int gemm_blocks = (NN + 127) / 128;
    const int agg_blocks = (NN * 32 + 255) / 256;
    const int apply_blocks = (NN * DD / 4 + 255) / 256;
    const int stats_blocks = (NN + 255) / 256;

    // layer 0
    agg_kernel<<<agg_blocks, 256>>>(x, aggp);
    gemm_mma<128, 2><<<gemm_blocks, 256, SMEM01>>>(aggp, x, w01hi, w01lo, bl0, b0p, DD);
    zero_stats_kernel<<<1, 256>>>();
    stats_kernel<<<stats_blocks, 128>>>(b0p);
    apply_kernel<<<apply_blocks, 256>>>(b0p, g0, be0);

    // layer 1
    agg_kernel<<<agg_blocks, 256>>>(b0p, aggp);
    gemm_mma<128, 2><<<gemm_blocks, 256, SMEM01>>>(aggp, b0p, w01hi + 128 * 256,
                                                   w01lo + 128 * 256, bl1, b1p, DD);
    zero_stats_kernel<<<1, 256>>>();
    stats_kernel<<<stats_blocks, 128>>>(b1p);
    apply_kernel<<<apply_blocks, 256>>>(b1p, g1, be1);

    // layer 2: PR = h1 @ [Wl2|Wr2|0], then fused agg(P)+R+bias+log_softmax
    gemm_mma<PRW, 1><<<gemm_blocks, 256, SMEM2>>>(b1p, b1p, w2hi, w2lo, nullptr, prp, PRW);
    agg_lsm_kernel<<<(NN + 7) / 8, 256>>>(prp, bl2, out);
}